// round 2
// baseline (speedup 1.0000x reference)
#include <cuda_runtime.h>

#define BB 8
#define LL 256
#define DD 256
#define KK 64
#define IPB 16

// scratch: projections
__device__ float g_qi[BB*LL*KK];    // [b][i][k]
__device__ float g_kjT[BB*KK*LL];   // [b][k][j]  (k-major for coalesced j loads)

__device__ __forceinline__ unsigned long long fma2u(unsigned long long a,
                                                    unsigned long long b,
                                                    unsigned long long c) {
    unsigned long long d;
    asm("fma.rn.f32x2 %0, %1, %2, %3;" : "=l"(d) : "l"(a), "l"(b), "l"(c));
    return d;
}

__device__ __forceinline__ float2 u2f2(unsigned long long v) {
    float2 r;
    asm("mov.b64 {%0, %1}, %2;" : "=f"(r.x), "=f"(r.y) : "l"(v));
    return r;
}

__device__ __forceinline__ float fast_tanh(float x) {
    float y;
    asm("tanh.approx.f32 %0, %1;" : "=f"(y) : "f"(x));
    return y;
}

// ---------------------------------------------------------------------------
// Kernel 1: qi[b,i,k] = x[b,i,:]·W1[k,0:256], kjT[b,k,j] = x[b,j,:]·W1[k,256:512]
// grid = B * (L/16) = 128 blocks, 256 threads
// ---------------------------------------------------------------------------
__global__ void __launch_bounds__(256, 1)
proj_kernel(const float* __restrict__ x, const float* __restrict__ W1) {
    __shared__ float xs[16 * DD];        // 16 KB
    __shared__ float ws[16 * 2 * DD];    // 32 KB (16 k-rows of W1)

    int b  = blockIdx.x >> 4;
    int r0 = (blockIdx.x & 15) << 4;
    int t  = threadIdx.x;

    float4* xs4 = (float4*)xs;
    const float4* xg = (const float4*)(x + (b * LL + r0) * DD);
    #pragma unroll
    for (int u = t; u < 16 * DD / 4; u += 256) xs4[u] = xg[u];

    int k = t & 15;       // k within chunk
    int r = t >> 4;       // row within tile (0..15)

    for (int kc = 0; kc < KK; kc += 16) {
        __syncthreads();  // (also covers xs on first iter; protects ws reuse after)
        float4* ws4 = (float4*)ws;
        const float4* wg = (const float4*)(W1 + kc * 2 * DD);
        #pragma unroll
        for (int u = t; u < 16 * 2 * DD / 4; u += 256) ws4[u] = wg[u];
        __syncthreads();

        const ulonglong2* xa = (const ulonglong2*)(xs + r * DD);
        const ulonglong2* wi = (const ulonglong2*)(ws + k * 2 * DD);
        const ulonglong2* wj = (const ulonglong2*)(ws + k * 2 * DD + DD);

        unsigned long long aq0 = 0ull, aq1 = 0ull, ak0 = 0ull, ak1 = 0ull;
        #pragma unroll 8
        for (int d4 = 0; d4 < DD / 4; d4++) {
            ulonglong2 xv  = xa[d4];
            ulonglong2 wiv = wi[d4];
            ulonglong2 wjv = wj[d4];
            aq0 = fma2u(xv.x, wiv.x, aq0);
            aq1 = fma2u(xv.y, wiv.y, aq1);
            ak0 = fma2u(xv.x, wjv.x, ak0);
            ak1 = fma2u(xv.y, wjv.y, ak1);
        }
        float2 f;
        float qs, ks;
        f = u2f2(aq0); qs  = f.x + f.y;
        f = u2f2(aq1); qs += f.x + f.y;
        f = u2f2(ak0); ks  = f.x + f.y;
        f = u2f2(ak1); ks += f.x + f.y;

        int kk = kc + k;
        int rg = r0 + r;
        g_qi [(b * LL + rg) * KK + kk] = qs;
        g_kjT[(b * KK + kk) * LL + rg] = ks;
    }
}

// ---------------------------------------------------------------------------
// Kernel 2: fused scores + softmax + context + concat
// grid = B * (L/IPB) = 128 blocks, 256 threads, dynamic smem ~107 KB
// SMEM partition (floats):
//   kjs    [KK*LL]   = 16384     (64 KB)  [k][j]
//   scores [IPB*LL]  =  4096     (16 KB)  [i][j]
//   attnT  [LL*20]   =  5120     (20 KB)  [j][i] padded row=20 (4-way conf writes,
//                                          16B-aligned rows for LDS.128 reads)
//   qis    [IPB*KK]  =  1024     ( 4 KB)
//   w2s    [KK]      =    64
// ---------------------------------------------------------------------------
#define S_KJ   0
#define S_SC   (KK*LL)
#define S_AT   (S_SC + IPB*LL)
#define S_QI   (S_AT + LL*20)
#define S_W2   (S_QI + IPB*KK)
#define SMEM2_FLOATS (S_W2 + KK)
#define SMEM2_BYTES  (SMEM2_FLOATS * 4)

__global__ void __launch_bounds__(256, 1)
attn_kernel(const float* __restrict__ x, const float* __restrict__ W2,
            float* __restrict__ out) {
    extern __shared__ float smem[];
    float* kjs     = smem + S_KJ;
    float* scoresS = smem + S_SC;
    float* attnT   = smem + S_AT;
    float* qis     = smem + S_QI;
    float* w2s     = smem + S_W2;

    int b  = blockIdx.x >> 4;
    int i0 = (blockIdx.x & 15) * IPB;
    int t  = threadIdx.x;           // = j in phase A, = d in phase C

    // stage kjT[b] (64KB contiguous) and qi tile
    {
        float4* kjs4 = (float4*)kjs;
        const float4* kg = (const float4*)(g_kjT + b * KK * LL);
        #pragma unroll
        for (int u = t; u < KK * LL / 4; u += 256) kjs4[u] = kg[u];
        float4* qis4 = (float4*)qis;
        const float4* qg = (const float4*)(g_qi + (b * LL + i0) * KK);
        #pragma unroll
        for (int u = t; u < IPB * KK / 4; u += 256) qis4[u] = qg[u];
        if (t < KK) w2s[t] = W2[t];
    }
    __syncthreads();

    // ---- Phase A: scores[i][t] = sum_k W2[k]*tanh(qi[i][k] + kj[k][t]) ----
    float sc[IPB];
    #pragma unroll
    for (int i = 0; i < IPB; i++) sc[i] = 0.f;

    #pragma unroll 4
    for (int k = 0; k < KK; k++) {
        float kv = kjs[k * LL + t];
        float wv = w2s[k];
        #pragma unroll
        for (int i = 0; i < IPB; i++) {
            float th = fast_tanh(qis[i * KK + k] + kv);
            sc[i] = fmaf(wv, th, sc[i]);
        }
    }
    #pragma unroll
    for (int i = 0; i < IPB; i++) scoresS[i * LL + t] = sc[i];
    __syncthreads();

    // ---- Phase B: softmax over j, warp w handles i = 2w, 2w+1 ----
    {
        int w = t >> 5, lane = t & 31;
        #pragma unroll
        for (int ii = 0; ii < 2; ii++) {
            int i = w * 2 + ii;
            float v[8];
            float mx = -1e30f;
            #pragma unroll
            for (int r = 0; r < 8; r++) {
                v[r] = scoresS[i * LL + lane + 32 * r];
                mx = fmaxf(mx, v[r]);
            }
            #pragma unroll
            for (int o = 16; o; o >>= 1) mx = fmaxf(mx, __shfl_xor_sync(0xffffffffu, mx, o));
            float s = 0.f;
            #pragma unroll
            for (int r = 0; r < 8; r++) { v[r] = __expf(v[r] - mx); s += v[r]; }
            #pragma unroll
            for (int o = 16; o; o >>= 1) s += __shfl_xor_sync(0xffffffffu, s, o);
            float inv = 1.f / s;
            #pragma unroll
            for (int r = 0; r < 8; r++)
                attnT[(lane + 32 * r) * 20 + i] = v[r] * inv;
        }
    }
    __syncthreads();

    // ---- Phase C: context[i][t] = sum_j attn[i][j] * x[b,j,t]; i pairs packed f32x2 ----
    unsigned long long accp[8];
    #pragma unroll
    for (int p = 0; p < 8; p++) accp[p] = 0ull;

    const float* xb = x + b * LL * DD;
    #pragma unroll 4
    for (int j = 0; j < LL; j++) {
        float xv = xb[j * DD + t];
        unsigned long long xx;
        asm("mov.b64 %0, {%1, %1};" : "=l"(xx) : "f"(xv));
        const ulonglong2* at = (const ulonglong2*)(attnT + j * 20);
        ulonglong2 q0 = at[0];
        ulonglong2 q1 = at[1];
        accp[0] = fma2u(q0.x, xx, accp[0]);
        accp[1] = fma2u(q0.y, xx, accp[1]);
        accp[2] = fma2u(q1.x, xx, accp[2]);
        accp[3] = fma2u(q1.y, xx, accp[3]);
        ulonglong2 q2 = at[2];
        ulonglong2 q3 = at[3];
        accp[4] = fma2u(q2.x, xx, accp[4]);
        accp[5] = fma2u(q2.y, xx, accp[5]);
        accp[6] = fma2u(q3.x, xx, accp[6]);
        accp[7] = fma2u(q3.y, xx, accp[7]);
    }

    // ---- Output: out[b, i0+i, 0:256] = x row copy; out[b, i0+i, 256:512] = ctx ----
    #pragma unroll
    for (int p = 0; p < 8; p++) {
        float2 c = u2f2(accp[p]);   // (i=2p, i=2p+1)
        int ia = i0 + 2 * p;
        int ib = ia + 1;
        float xa = xb[(i0 + 2 * p) * DD + t];
        float xbv = xb[(i0 + 2 * p + 1) * DD + t];
        float* rowa = out + (unsigned)(b * LL + ia) * (2 * DD);
        float* rowb = out + (unsigned)(b * LL + ib) * (2 * DD);
        rowa[t]      = xa;
        rowa[DD + t] = c.x;
        rowb[t]      = xbv;
        rowb[DD + t] = c.y;
    }
}

// ---------------------------------------------------------------------------
extern "C" void kernel_launch(void* const* d_in, const int* in_sizes, int n_in,
                              void* d_out, int out_size) {
    const float* x  = (const float*)d_in[0];   // (8,256,256)
    const float* W1 = (const float*)d_in[1];   // (64,512)
    const float* W2 = (const float*)d_in[2];   // (1,64)
    float* out = (float*)d_out;                // (8,256,512)

    proj_kernel<<<BB * (LL / 16), 256>>>(x, W1);

    cudaFuncSetAttribute(attn_kernel,
                         cudaFuncAttributeMaxDynamicSharedMemorySize,
                         SMEM2_BYTES);
    attn_kernel<<<BB * (LL / IPB), 256, SMEM2_BYTES>>>(x, W2, out);
}

// round 3
// speedup vs baseline: 1.9852x; 1.9852x over previous
#include <cuda_runtime.h>

#define BB 8
#define LL 256
#define DD 256
#define KK 64
#define IPB 16

#define TANH_C 2.885390081777927f   // 2*log2(e): e^(2x) = exp2(C*x)

// scratch: projections, PRE-SCALED by TANH_C
__device__ float g_qi[BB*LL*KK];    // [b][i][k]
__device__ float g_kjT[BB*KK*LL];   // [b][k][j]  (k-major for coalesced j loads)

__device__ __forceinline__ unsigned long long fma2u(unsigned long long a,
                                                    unsigned long long b,
                                                    unsigned long long c) {
    unsigned long long d;
    asm("fma.rn.f32x2 %0, %1, %2, %3;" : "=l"(d) : "l"(a), "l"(b), "l"(c));
    return d;
}

__device__ __forceinline__ float2 u2f2(unsigned long long v) {
    float2 r;
    asm("mov.b64 {%0, %1}, %2;" : "=f"(r.x), "=f"(r.y) : "l"(v));
    return r;
}

__device__ __forceinline__ float fast_ex2(float x) {
    float y; asm("ex2.approx.f32 %0, %1;" : "=f"(y) : "f"(x)); return y;
}
__device__ __forceinline__ float fast_rcp(float x) {
    float y; asm("rcp.approx.f32 %0, %1;" : "=f"(y) : "f"(x)); return y;
}

// ---------------------------------------------------------------------------
// Kernel 1: qi[b,i,k] = C * x[b,i,:]·W1[k,0:256], kjT[b,k,j] = C * x[b,j,:]·W1[k,256:512]
// grid = B * (L/16) = 128 blocks, 256 threads
// Thread map: k = t>>4 (W1 reads broadcast within 16-lane groups -> conflict-free),
//             r = t&15 (x rows padded to stride 260 floats -> banks covered evenly).
// ---------------------------------------------------------------------------
#define XPAD 260   // floats per padded x row (65 float4)

__global__ void __launch_bounds__(256, 1)
proj_kernel(const float* __restrict__ x, const float* __restrict__ W1) {
    __shared__ float xs[16 * XPAD];      // ~16.6 KB
    __shared__ float ws[16 * 2 * DD];    // 32 KB (16 k-rows of W1)

    int b  = blockIdx.x >> 4;
    int r0 = (blockIdx.x & 15) << 4;
    int t  = threadIdx.x;

    // stage x tile with padded rows
    {
        float4* xs4 = (float4*)xs;
        const float4* xg = (const float4*)(x + (b * LL + r0) * DD);
        #pragma unroll
        for (int u = t; u < 16 * DD / 4; u += 256) {
            int row = u >> 6;          // 64 float4 per logical row
            int c4  = u & 63;
            xs4[row * (XPAD / 4) + c4] = xg[u];
        }
    }

    int k = t >> 4;       // k within chunk (0..15)
    int r = t & 15;       // row within tile (0..15)

    for (int kc = 0; kc < KK; kc += 16) {
        __syncthreads();  // covers xs on first iter; protects ws reuse after
        float4* ws4 = (float4*)ws;
        const float4* wg = (const float4*)(W1 + kc * 2 * DD);
        #pragma unroll
        for (int u = t; u < 16 * 2 * DD / 4; u += 256) ws4[u] = wg[u];
        __syncthreads();

        const ulonglong2* xa = (const ulonglong2*)(xs + r * XPAD);
        const ulonglong2* wi = (const ulonglong2*)(ws + k * 2 * DD);
        const ulonglong2* wj = (const ulonglong2*)(ws + k * 2 * DD + DD);

        unsigned long long aq0 = 0ull, aq1 = 0ull, ak0 = 0ull, ak1 = 0ull;
        #pragma unroll 8
        for (int d4 = 0; d4 < DD / 4; d4++) {
            ulonglong2 xv  = xa[d4];
            ulonglong2 wiv = wi[d4];
            ulonglong2 wjv = wj[d4];
            aq0 = fma2u(xv.x, wiv.x, aq0);
            aq1 = fma2u(xv.y, wiv.y, aq1);
            ak0 = fma2u(xv.x, wjv.x, ak0);
            ak1 = fma2u(xv.y, wjv.y, ak1);
        }
        float2 f;
        float qs, ks;
        f = u2f2(aq0); qs  = f.x + f.y;
        f = u2f2(aq1); qs += f.x + f.y;
        f = u2f2(ak0); ks  = f.x + f.y;
        f = u2f2(ak1); ks += f.x + f.y;

        int kk = kc + k;
        int rg = r0 + r;
        g_qi [(b * LL + rg) * KK + kk] = qs * TANH_C;   // pre-scaled
        g_kjT[(b * KK + kk) * LL + rg] = ks * TANH_C;   // pre-scaled
    }
}

// ---------------------------------------------------------------------------
// Kernel 2: fused scores + softmax + context + concat
// grid = B * (L/IPB) = 128 blocks, 256 threads, dynamic smem ~107 KB
// ---------------------------------------------------------------------------
#define S_KJ   0
#define S_SC   (KK*LL)
#define S_AT   (S_SC + IPB*LL)
#define S_QI   (S_AT + LL*20)
#define S_W2   (S_QI + IPB*KK)
#define SMEM2_FLOATS (S_W2 + KK)
#define SMEM2_BYTES  (SMEM2_FLOATS * 4)

__global__ void __launch_bounds__(256, 1)
attn_kernel(const float* __restrict__ x, const float* __restrict__ W2,
            float* __restrict__ out) {
    extern __shared__ float smem[];
    float* kjs     = smem + S_KJ;
    float* scoresS = smem + S_SC;
    float* attnT   = smem + S_AT;
    float* qis     = smem + S_QI;
    float* w2s     = smem + S_W2;

    int b  = blockIdx.x >> 4;
    int i0 = (blockIdx.x & 15) * IPB;
    int t  = threadIdx.x;           // = j in phase A, = d in phase C

    // stage kjT[b] (64KB contiguous, pre-scaled) and qi tile (pre-scaled)
    {
        float4* kjs4 = (float4*)kjs;
        const float4* kg = (const float4*)(g_kjT + b * KK * LL);
        #pragma unroll
        for (int u = t; u < KK * LL / 4; u += 256) kjs4[u] = kg[u];
        float4* qis4 = (float4*)qis;
        const float4* qg = (const float4*)(g_qi + (b * LL + i0) * KK);
        #pragma unroll
        for (int u = t; u < IPB * KK / 4; u += 256) qis4[u] = qg[u];
        if (t < KK) w2s[t] = W2[t];
    }
    __syncthreads();

    // ---- Phase A: scores via tanh(x) = 1 - 2/(1+e^{2x}); e^{2x} = exp2(qs+ks)
    //      (qs, ks pre-scaled by 2*log2e). Score = sumW - 2*sum_k w_k*r_k;
    //      the sumW constant is identical for all (i,j) -> softmax-invariant -> dropped.
    float acc[IPB];
    #pragma unroll
    for (int i = 0; i < IPB; i++) acc[i] = 0.f;

    #pragma unroll 4
    for (int k = 0; k < KK; k++) {
        float kv = kjs[k * LL + t];
        float wv = w2s[k];
        #pragma unroll
        for (int i = 0; i < IPB; i++) {
            float ts = qis[i * KK + k] + kv;     // = 2x*log2e
            float e  = fast_ex2(ts);             // e^{2x}   (inf ok: r->0)
            float r  = fast_rcp(e + 1.0f);       // 1/(1+e^{2x})
            acc[i] = fmaf(wv, r, acc[i]);
        }
    }
    #pragma unroll
    for (int i = 0; i < IPB; i++) scoresS[i * LL + t] = -2.0f * acc[i];
    __syncthreads();

    // ---- Phase B: softmax over j, warp w handles i = 2w, 2w+1 ----
    {
        int w = t >> 5, lane = t & 31;
        #pragma unroll
        for (int ii = 0; ii < 2; ii++) {
            int i = w * 2 + ii;
            float v[8];
            float mx = -1e30f;
            #pragma unroll
            for (int r = 0; r < 8; r++) {
                v[r] = scoresS[i * LL + lane + 32 * r];
                mx = fmaxf(mx, v[r]);
            }
            #pragma unroll
            for (int o = 16; o; o >>= 1) mx = fmaxf(mx, __shfl_xor_sync(0xffffffffu, mx, o));
            float s = 0.f;
            #pragma unroll
            for (int r = 0; r < 8; r++) { v[r] = __expf(v[r] - mx); s += v[r]; }
            #pragma unroll
            for (int o = 16; o; o >>= 1) s += __shfl_xor_sync(0xffffffffu, s, o);
            float inv = 1.f / s;
            #pragma unroll
            for (int r = 0; r < 8; r++)
                attnT[(lane + 32 * r) * 20 + i] = v[r] * inv;
        }
    }
    __syncthreads();

    // ---- Phase C: context[i][t] = sum_j attn[i][j] * x[b,j,t]; i pairs packed f32x2 ----
    unsigned long long accp[8];
    #pragma unroll
    for (int p = 0; p < 8; p++) accp[p] = 0ull;

    const float* xb = x + b * LL * DD;
    #pragma unroll 4
    for (int j = 0; j < LL; j++) {
        float xv = xb[j * DD + t];
        unsigned long long xx;
        asm("mov.b64 %0, {%1, %1};" : "=l"(xx) : "f"(xv));
        const ulonglong2* at = (const ulonglong2*)(attnT + j * 20);
        ulonglong2 q0 = at[0];
        ulonglong2 q1 = at[1];
        accp[0] = fma2u(q0.x, xx, accp[0]);
        accp[1] = fma2u(q0.y, xx, accp[1]);
        accp[2] = fma2u(q1.x, xx, accp[2]);
        accp[3] = fma2u(q1.y, xx, accp[3]);
        ulonglong2 q2 = at[2];
        ulonglong2 q3 = at[3];
        accp[4] = fma2u(q2.x, xx, accp[4]);
        accp[5] = fma2u(q2.y, xx, accp[5]);
        accp[6] = fma2u(q3.x, xx, accp[6]);
        accp[7] = fma2u(q3.y, xx, accp[7]);
    }

    // ---- Output: out[b, i0+i, 0:256] = x row copy; out[b, i0+i, 256:512] = ctx ----
    #pragma unroll
    for (int p = 0; p < 8; p++) {
        float2 c = u2f2(accp[p]);   // (i=2p, i=2p+1)
        int ia = i0 + 2 * p;
        int ib = ia + 1;
        float xa  = xb[ia * DD + t];
        float xbv = xb[ib * DD + t];
        float* rowa = out + (unsigned)(b * LL + ia) * (2 * DD);
        float* rowb = out + (unsigned)(b * LL + ib) * (2 * DD);
        rowa[t]      = xa;
        rowa[DD + t] = c.x;
        rowb[t]      = xbv;
        rowb[DD + t] = c.y;
    }
}

// ---------------------------------------------------------------------------
extern "C" void kernel_launch(void* const* d_in, const int* in_sizes, int n_in,
                              void* d_out, int out_size) {
    const float* x  = (const float*)d_in[0];   // (8,256,256)
    const float* W1 = (const float*)d_in[1];   // (64,512)
    const float* W2 = (const float*)d_in[2];   // (1,64)
    float* out = (float*)d_out;                // (8,256,512)

    proj_kernel<<<BB * (LL / 16), 256>>>(x, W1);

    static int smem_set = 0;
    if (!smem_set) {
        cudaFuncSetAttribute(attn_kernel,
                             cudaFuncAttributeMaxDynamicSharedMemorySize,
                             SMEM2_BYTES);
        smem_set = 1;
    }
    attn_kernel<<<BB * (LL / IPB), 256, SMEM2_BYTES>>>(x, W2, out);
}

// round 6
// speedup vs baseline: 2.1583x; 1.0872x over previous
#include <cuda_runtime.h>

#define BB 8
#define LL 256
#define DD 256
#define KK 64
#define IPB 16

#define TANH_C 2.885390081777927f   // 2*log2(e): e^(2x) = exp2(C*x)

// scratch: projections, PRE-SCALED by TANH_C
__device__ float g_qi[BB*LL*KK];    // [b][i][k]
__device__ float g_kjT[BB*KK*LL];   // [b][k][j]  (k-major for coalesced j loads)

__device__ __forceinline__ unsigned long long fma2u(unsigned long long a,
                                                    unsigned long long b,
                                                    unsigned long long c) {
    unsigned long long d;
    asm("fma.rn.f32x2 %0, %1, %2, %3;" : "=l"(d) : "l"(a), "l"(b), "l"(c));
    return d;
}

__device__ __forceinline__ float2 u2f2(unsigned long long v) {
    float2 r;
    asm("mov.b64 {%0, %1}, %2;" : "=f"(r.x), "=f"(r.y) : "l"(v));
    return r;
}

__device__ __forceinline__ float fast_ex2(float x) {
    float y; asm("ex2.approx.f32 %0, %1;" : "=f"(y) : "f"(x)); return y;
}
__device__ __forceinline__ float fast_rcp(float x) {
    float y; asm("rcp.approx.f32 %0, %1;" : "=f"(y) : "f"(x)); return y;
}

// ---------------------------------------------------------------------------
// Kernel 1: qi[b,i,k] = C * x[b,i,:]·W1[k,0:256], kjT[b,k,j] = C * x[b,j,:]·W1[k,256:512]
// grid = 128 blocks, 512 threads, dynamic smem ~81 KB (xs padded + 32 W1 rows)
// Thread map: k = t>>4 (0..31, W1 reads broadcast in 16-lane groups),
//             r = t&15 (x rows padded to stride 260 -> 2-way max conflicts).
// ---------------------------------------------------------------------------
#define XPAD 260   // floats per padded x row (65 float4)
#define P_XS 0
#define P_WS (16 * XPAD)
#define PROJ_SMEM_FLOATS (P_WS + 32 * 2 * DD)
#define PROJ_SMEM_BYTES  (PROJ_SMEM_FLOATS * 4)

__global__ void __launch_bounds__(512, 1)
proj_kernel(const float* __restrict__ x, const float* __restrict__ W1) {
    extern __shared__ float psm[];
    float* xs = psm + P_XS;
    float* ws = psm + P_WS;

    int b  = blockIdx.x >> 4;
    int r0 = (blockIdx.x & 15) << 4;
    int t  = threadIdx.x;

    // stage x tile with padded rows (1024 float4 / 512 thr = 2 each)
    {
        float4* xs4 = (float4*)xs;
        const float4* xg = (const float4*)(x + (b * LL + r0) * DD);
        #pragma unroll
        for (int u = t; u < 16 * DD / 4; u += 512) {
            int row = u >> 6;          // 64 float4 per logical row
            int c4  = u & 63;
            xs4[row * (XPAD / 4) + c4] = xg[u];
        }
    }

    int k = t >> 4;       // k within chunk (0..31)
    int r = t & 15;       // row within tile (0..15)

    #pragma unroll
    for (int kc = 0; kc < KK; kc += 32) {
        __syncthreads();  // covers xs on first iter; protects ws reuse after
        float4* ws4 = (float4*)ws;
        const float4* wg = (const float4*)(W1 + kc * 2 * DD);
        #pragma unroll
        for (int u = t; u < 32 * 2 * DD / 4; u += 512) ws4[u] = wg[u];
        __syncthreads();

        const ulonglong2* xa = (const ulonglong2*)(xs + r * XPAD);
        const ulonglong2* wi = (const ulonglong2*)(ws + k * 2 * DD);
        const ulonglong2* wj = (const ulonglong2*)(ws + k * 2 * DD + DD);

        unsigned long long aq0 = 0ull, aq1 = 0ull, ak0 = 0ull, ak1 = 0ull;
        #pragma unroll 8
        for (int d4 = 0; d4 < DD / 4; d4++) {
            ulonglong2 xv  = xa[d4];
            ulonglong2 wiv = wi[d4];
            ulonglong2 wjv = wj[d4];
            aq0 = fma2u(xv.x, wiv.x, aq0);
            aq1 = fma2u(xv.y, wiv.y, aq1);
            ak0 = fma2u(xv.x, wjv.x, ak0);
            ak1 = fma2u(xv.y, wjv.y, ak1);
        }
        float2 f;
        float qs, ks;
        f = u2f2(aq0); qs  = f.x + f.y;
        f = u2f2(aq1); qs += f.x + f.y;
        f = u2f2(ak0); ks  = f.x + f.y;
        f = u2f2(ak1); ks += f.x + f.y;

        int kk = kc + k;
        int rg = r0 + r;
        g_qi [(b * LL + rg) * KK + kk] = qs * TANH_C;   // pre-scaled
        g_kjT[(b * KK + kk) * LL + rg] = ks * TANH_C;   // pre-scaled
    }
}

// ---------------------------------------------------------------------------
// Kernel 2: fused scores + softmax + context + concat
// grid = 128 blocks, 512 threads (i-split across thread halves), ~107 KB smem
// ---------------------------------------------------------------------------
#define S_KJ   0
#define S_SC   (KK*LL)
#define S_AT   (S_SC + IPB*LL)
#define S_QI   (S_AT + LL*20)
#define S_W2   (S_QI + IPB*KK)
#define SMEM2_FLOATS (S_W2 + KK)
#define SMEM2_BYTES  (SMEM2_FLOATS * 4)

__global__ void __launch_bounds__(512, 1)
attn_kernel(const float* __restrict__ x, const float* __restrict__ W2,
            float* __restrict__ out) {
    extern __shared__ float smem[];
    float* kjs     = smem + S_KJ;
    float* scoresS = smem + S_SC;
    float* attnT   = smem + S_AT;
    float* qis     = smem + S_QI;
    float* w2s     = smem + S_W2;

    int b    = blockIdx.x >> 4;
    int i0   = (blockIdx.x & 15) * IPB;
    int t    = threadIdx.x;
    int tj   = t & 255;        // j in phase A, d in phase C
    int half = t >> 8;         // 0: i 0-7, 1: i 8-15

    // stage kjT[b] (64KB), qi tile (4KB), W2
    {
        float4* kjs4 = (float4*)kjs;
        const float4* kg = (const float4*)(g_kjT + b * KK * LL);
        #pragma unroll
        for (int u = t; u < KK * LL / 4; u += 512) kjs4[u] = kg[u];
        float4* qis4 = (float4*)qis;
        const float4* qg = (const float4*)(g_qi + (b * LL + i0) * KK);
        if (t < IPB * KK / 4) qis4[t] = qg[t];
        if (t < KK) w2s[t] = W2[t];
    }
    __syncthreads();

    // ---- Phase A: tanh via 1 - 2/(1+e^{2x}); e^{2x} = exp2(qs+ks), pre-scaled.
    //      Constant sumW term is softmax-invariant -> dropped.
    float acc[8];
    #pragma unroll
    for (int i = 0; i < 8; i++) acc[i] = 0.f;

    const float* qbase = qis + half * 8 * KK;

    #pragma unroll 4
    for (int k = 0; k < KK; k++) {
        float kv = kjs[k * LL + tj];
        float wv = w2s[k];
        #pragma unroll
        for (int i = 0; i < 8; i++) {
            float ts = qbase[i * KK + k] + kv;   // 2x*log2e
            float e  = fast_ex2(ts);
            float r  = fast_rcp(e + 1.0f);
            acc[i] = fmaf(wv, r, acc[i]);
        }
    }
    #pragma unroll
    for (int i = 0; i < 8; i++)
        scoresS[(half * 8 + i) * LL + tj] = -2.0f * acc[i];
    __syncthreads();

    // ---- Phase B: softmax over j; warp w handles i = w (16 warps, 16 rows) ----
    {
        int w = t >> 5, lane = t & 31;
        float v[8];
        float mx = -1e30f;
        #pragma unroll
        for (int r = 0; r < 8; r++) {
            v[r] = scoresS[w * LL + lane + 32 * r];
            mx = fmaxf(mx, v[r]);
        }
        #pragma unroll
        for (int o = 16; o; o >>= 1) mx = fmaxf(mx, __shfl_xor_sync(0xffffffffu, mx, o));
        float s = 0.f;
        #pragma unroll
        for (int r = 0; r < 8; r++) { v[r] = __expf(v[r] - mx); s += v[r]; }
        #pragma unroll
        for (int o = 16; o; o >>= 1) s += __shfl_xor_sync(0xffffffffu, s, o);
        float inv = 1.f / s;
        #pragma unroll
        for (int r = 0; r < 8; r++)
            attnT[(lane + 32 * r) * 20 + w] = v[r] * inv;
    }
    __syncthreads();

    // ---- Phase C: context[i][tj] = sum_j attn[i][j]*x[b,j,tj]; this half's 8 i's
    //      as 4 packed f32x2 pairs; attnT reads are warp-broadcast LDS.128 ----
    unsigned long long accp[4];
    #pragma unroll
    for (int p = 0; p < 4; p++) accp[p] = 0ull;

    const float* xb = x + b * LL * DD;
    #pragma unroll 4
    for (int j = 0; j < LL; j++) {
        float xv = xb[j * DD + tj];
        unsigned long long xx;
        asm("mov.b64 %0, {%1, %1};" : "=l"(xx) : "f"(xv));
        const ulonglong2* at = (const ulonglong2*)(attnT + j * 20 + half * 8);
        ulonglong2 q0 = at[0];
        ulonglong2 q1 = at[1];
        accp[0] = fma2u(q0.x, xx, accp[0]);
        accp[1] = fma2u(q0.y, xx, accp[1]);
        accp[2] = fma2u(q1.x, xx, accp[2]);
        accp[3] = fma2u(q1.y, xx, accp[3]);
    }

    // ---- Output: rows for this half's 8 i's ----
    #pragma unroll
    for (int p = 0; p < 4; p++) {
        float2 c = u2f2(accp[p]);   // (i=half*8+2p, +1)
        int ia = i0 + half * 8 + 2 * p;
        int ib = ia + 1;
        float xa  = xb[(half * 8 + 2 * p + i0) * DD + tj];
        float xbv = xb[(half * 8 + 2 * p + 1 + i0) * DD + tj];
        float* rowa = out + (unsigned)(b * LL + ia) * (2 * DD);
        float* rowb = out + (unsigned)(b * LL + ib) * (2 * DD);
        rowa[tj]      = xa;
        rowa[DD + tj] = c.x;
        rowb[tj]      = xbv;
        rowb[DD + tj] = c.y;
    }
}

// ---------------------------------------------------------------------------
extern "C" void kernel_launch(void* const* d_in, const int* in_sizes, int n_in,
                              void* d_out, int out_size) {
    const float* x  = (const float*)d_in[0];   // (8,256,256)
    const float* W1 = (const float*)d_in[1];   // (64,512)
    const float* W2 = (const float*)d_in[2];   // (1,64)
    float* out = (float*)d_out;                // (8,256,512)

    cudaFuncSetAttribute(proj_kernel,
                         cudaFuncAttributeMaxDynamicSharedMemorySize,
                         PROJ_SMEM_BYTES);
    proj_kernel<<<BB * (LL / 16), 512, PROJ_SMEM_BYTES>>>(x, W1);

    cudaFuncSetAttribute(attn_kernel,
                         cudaFuncAttributeMaxDynamicSharedMemorySize,
                         SMEM2_BYTES);
    attn_kernel<<<BB * (LL / IPB), 512, SMEM2_BYTES>>>(x, W2, out);
}

// round 7
// speedup vs baseline: 2.1950x; 1.0170x over previous
#include <cuda_runtime.h>

#define BB 8
#define LL 256
#define DD 256
#define KK 64
#define IPB 16

#define TANH_C 2.885390081777927f   // 2*log2(e): e^(2x) = exp2(C*x)

// scratch: projections, PRE-SCALED by TANH_C
__device__ float g_qi[BB*LL*KK];    // [b][i][k]
__device__ float g_kjT[BB*KK*LL];   // [b][k][j]  (k-major for coalesced j loads)

__device__ __forceinline__ unsigned long long fma2u(unsigned long long a,
                                                    unsigned long long b,
                                                    unsigned long long c) {
    unsigned long long d;
    asm("fma.rn.f32x2 %0, %1, %2, %3;" : "=l"(d) : "l"(a), "l"(b), "l"(c));
    return d;
}
__device__ __forceinline__ unsigned long long mul2u(unsigned long long a,
                                                    unsigned long long b) {
    unsigned long long d;
    asm("mul.rn.f32x2 %0, %1, %2;" : "=l"(d) : "l"(a), "l"(b));
    return d;
}
__device__ __forceinline__ unsigned long long add2u(unsigned long long a,
                                                    unsigned long long b) {
    unsigned long long d;
    asm("add.rn.f32x2 %0, %1, %2;" : "=l"(d) : "l"(a), "l"(b));
    return d;
}
__device__ __forceinline__ float2 u2f2(unsigned long long v) {
    float2 r;
    asm("mov.b64 {%0, %1}, %2;" : "=f"(r.x), "=f"(r.y) : "l"(v));
    return r;
}
__device__ __forceinline__ unsigned long long dupf(float v) {
    unsigned long long d;
    asm("mov.b64 %0, {%1, %1};" : "=l"(d) : "f"(v));
    return d;
}
__device__ __forceinline__ float fast_ex2(float x) {
    float y; asm("ex2.approx.f32 %0, %1;" : "=f"(y) : "f"(x)); return y;
}

// acc += wv2 * y' where y' -> -1/(1+exp2(q+kv)), per packed pair.
// Magic 0xFEF311C3 = reciprocal magic with sign bit folded in (negative guess),
// so Newton y1' = y0'*(2 + d*y0') needs no negations.
__device__ __forceinline__ void sig_acc(unsigned long long q2,
                                        unsigned long long kv2,
                                        unsigned long long wv2,
                                        unsigned long long two2,
                                        unsigned long long& acc) {
    unsigned long long ts2 = add2u(q2, kv2);
    float t0, t1;
    asm("mov.b64 {%0, %1}, %2;" : "=f"(t0), "=f"(t1) : "l"(ts2));
    float e0 = fast_ex2(t0), e1 = fast_ex2(t1);
    float d0 = e0 + 1.0f,    d1 = e1 + 1.0f;
    unsigned u0 = 0xFEF311C3u - __float_as_uint(d0);
    unsigned u1 = 0xFEF311C3u - __float_as_uint(d1);
    unsigned long long dp, yp, s;
    asm("mov.b64 %0, {%1, %2};" : "=l"(dp) : "f"(d0), "f"(d1));
    asm("mov.b64 %0, {%1, %2};" : "=l"(yp) : "r"(u0), "r"(u1));
    s = fma2u(dp, yp, two2);  yp = mul2u(yp, s);
    s = fma2u(dp, yp, two2);  yp = mul2u(yp, s);
    acc = fma2u(wv2, yp, acc);
}

// ---------------------------------------------------------------------------
// Kernel 1: qi[b,i,k] = C * x[b,i,:]·W1[k,0:256], kjT[b,k,j] = C * x[b,j,:]·W1[k,256:512]
// grid = 128 blocks, 512 threads, dynamic smem ~81 KB
// ---------------------------------------------------------------------------
#define XPAD 260   // floats per padded x row (65 float4)
#define P_XS 0
#define P_WS (16 * XPAD)
#define PROJ_SMEM_FLOATS (P_WS + 32 * 2 * DD)
#define PROJ_SMEM_BYTES  (PROJ_SMEM_FLOATS * 4)

__global__ void __launch_bounds__(512, 1)
proj_kernel(const float* __restrict__ x, const float* __restrict__ W1) {
    extern __shared__ float psm[];
    float* xs = psm + P_XS;
    float* ws = psm + P_WS;

    int b  = blockIdx.x >> 4;
    int r0 = (blockIdx.x & 15) << 4;
    int t  = threadIdx.x;

    {
        float4* xs4 = (float4*)xs;
        const float4* xg = (const float4*)(x + (b * LL + r0) * DD);
        #pragma unroll
        for (int u = t; u < 16 * DD / 4; u += 512) {
            int row = u >> 6;
            int c4  = u & 63;
            xs4[row * (XPAD / 4) + c4] = xg[u];
        }
    }

    int k = t >> 4;
    int r = t & 15;

    #pragma unroll
    for (int kc = 0; kc < KK; kc += 32) {
        __syncthreads();
        float4* ws4 = (float4*)ws;
        const float4* wg = (const float4*)(W1 + kc * 2 * DD);
        #pragma unroll
        for (int u = t; u < 32 * 2 * DD / 4; u += 512) ws4[u] = wg[u];
        __syncthreads();

        const ulonglong2* xa = (const ulonglong2*)(xs + r * XPAD);
        const ulonglong2* wi = (const ulonglong2*)(ws + k * 2 * DD);
        const ulonglong2* wj = (const ulonglong2*)(ws + k * 2 * DD + DD);

        unsigned long long aq0 = 0ull, aq1 = 0ull, ak0 = 0ull, ak1 = 0ull;
        #pragma unroll 8
        for (int d4 = 0; d4 < DD / 4; d4++) {
            ulonglong2 xv  = xa[d4];
            ulonglong2 wiv = wi[d4];
            ulonglong2 wjv = wj[d4];
            aq0 = fma2u(xv.x, wiv.x, aq0);
            aq1 = fma2u(xv.y, wiv.y, aq1);
            ak0 = fma2u(xv.x, wjv.x, ak0);
            ak1 = fma2u(xv.y, wjv.y, ak1);
        }
        float2 f;
        float qs, ks;
        f = u2f2(aq0); qs  = f.x + f.y;
        f = u2f2(aq1); qs += f.x + f.y;
        f = u2f2(ak0); ks  = f.x + f.y;
        f = u2f2(ak1); ks += f.x + f.y;

        int kk = kc + k;
        int rg = r0 + r;
        g_qi [(b * LL + rg) * KK + kk] = qs * TANH_C;
        g_kjT[(b * KK + kk) * LL + rg] = ks * TANH_C;
    }
}

// ---------------------------------------------------------------------------
// Kernel 2: fused scores + softmax + context + concat
// grid = 128 blocks, 1024 threads (i split 4-way by thread quarter), ~104 KB smem
// ---------------------------------------------------------------------------
#define S_KJ   0
#define S_SC   (KK*LL)
#define S_AT   (S_SC + IPB*LL)
#define S_QT   (S_AT + LL*20)
#define S_W2   (S_QT + KK*IPB)
#define SMEM2_FLOATS (S_W2 + KK)
#define SMEM2_BYTES  (SMEM2_FLOATS * 4)

__global__ void __launch_bounds__(1024, 1)
attn_kernel(const float* __restrict__ x, const float* __restrict__ W2,
            float* __restrict__ out) {
    extern __shared__ float smem[];
    float* kjs     = smem + S_KJ;     // [k][j]   64x256
    float* scoresS = smem + S_SC;     // [i][j]   16x256
    float* attnT   = smem + S_AT;     // [j][i]   256x20 (pad)
    float* qis_t   = smem + S_QT;     // [k][i]   64x16  (transposed: i-pairs packable)
    float* w2s     = smem + S_W2;     // 2*W2

    int b    = blockIdx.x >> 4;
    int i0   = (blockIdx.x & 15) * IPB;
    int t    = threadIdx.x;
    int tj   = t & 255;        // j in phase A, d in phase C
    int quarter = t >> 8;      // i-range = quarter*4 .. +4

    // stage kjT[b] (64KB), qi tile transposed, W2 pre-doubled
    {
        float4* kjs4 = (float4*)kjs;
        const float4* kg = (const float4*)(g_kjT + b * KK * LL);
        #pragma unroll
        for (int u = t; u < KK * LL / 4; u += 1024) kjs4[u] = kg[u];
        // qis_t[k][i] = g_qi[b, i0+i, k]
        {
            int i = t >> 6, k = t & 63;   // t < 1024 covers all 16x64
            qis_t[k * IPB + i] = g_qi[(b * LL + i0 + i) * KK + k];
        }
        if (t < KK) w2s[t] = 2.0f * W2[t];
    }
    __syncthreads();

    // ---- Phase A: score'(i,j) = sum_k (2 w_k) * y'(q_ik + k_kj)
    //      where y' = -1/(1+e^{2x}); equals true score minus a softmax-invariant const.
    unsigned long long acc0 = 0ull, acc1 = 0ull;
    unsigned long long two2 = dupf(2.0f);
    const float* qt = qis_t + quarter * 4;

    #pragma unroll 2
    for (int k = 0; k < KK; k++) {
        float kv = kjs[k * LL + tj];
        float wv = w2s[k];
        unsigned long long kv2 = dupf(kv);
        unsigned long long wv2 = dupf(wv);
        unsigned long long q01 = *(const unsigned long long*)(qt + k * IPB);
        unsigned long long q23 = *(const unsigned long long*)(qt + k * IPB + 2);
        sig_acc(q01, kv2, wv2, two2, acc0);
        sig_acc(q23, kv2, wv2, two2, acc1);
    }
    {
        float2 a0 = u2f2(acc0), a1 = u2f2(acc1);
        int ib = quarter * 4;
        scoresS[(ib + 0) * LL + tj] = a0.x;
        scoresS[(ib + 1) * LL + tj] = a0.y;
        scoresS[(ib + 2) * LL + tj] = a1.x;
        scoresS[(ib + 3) * LL + tj] = a1.y;
    }
    __syncthreads();

    // ---- Phase B: softmax over j; warps 0-15 handle one i each ----
    if (t < 512) {
        int w = t >> 5, lane = t & 31;
        float v[8];
        float mx = -1e30f;
        #pragma unroll
        for (int r = 0; r < 8; r++) {
            v[r] = scoresS[w * LL + lane + 32 * r];
            mx = fmaxf(mx, v[r]);
        }
        #pragma unroll
        for (int o = 16; o; o >>= 1) mx = fmaxf(mx, __shfl_xor_sync(0xffffffffu, mx, o));
        float s = 0.f;
        #pragma unroll
        for (int r = 0; r < 8; r++) { v[r] = __expf(v[r] - mx); s += v[r]; }
        #pragma unroll
        for (int o = 16; o; o >>= 1) s += __shfl_xor_sync(0xffffffffu, s, o);
        float inv = 1.f / s;
        #pragma unroll
        for (int r = 0; r < 8; r++)
            attnT[(lane + 32 * r) * 20 + w] = v[r] * inv;
    }
    __syncthreads();

    // ---- Phase C: context[i][tj] = sum_j attn[i][j]*x[b,j,tj]; 4 i's = 2 f32x2 pairs ----
    unsigned long long accp0 = 0ull, accp1 = 0ull;
    const float* xb = x + b * LL * DD;
    #pragma unroll 4
    for (int j = 0; j < LL; j++) {
        float xv = xb[j * DD + tj];
        unsigned long long xx = dupf(xv);
        const ulonglong2* at = (const ulonglong2*)(attnT + j * 20 + quarter * 4);
        ulonglong2 q = *at;
        accp0 = fma2u(q.x, xx, accp0);
        accp1 = fma2u(q.y, xx, accp1);
    }

    // ---- Output rows for this quarter's 4 i's ----
    {
        float2 c0 = u2f2(accp0), c1 = u2f2(accp1);
        float cs[4] = {c0.x, c0.y, c1.x, c1.y};
        #pragma unroll
        for (int p = 0; p < 4; p++) {
            int il = quarter * 4 + p;
            int ia = i0 + il;
            float xv = xb[(i0 + il) * DD + tj];
            float* row = out + (unsigned)(b * LL + ia) * (2 * DD);
            row[tj]      = xv;
            row[DD + tj] = cs[p];
        }
    }
}

// ---------------------------------------------------------------------------
extern "C" void kernel_launch(void* const* d_in, const int* in_sizes, int n_in,
                              void* d_out, int out_size) {
    const float* x  = (const float*)d_in[0];   // (8,256,256)
    const float* W1 = (const float*)d_in[1];   // (64,512)
    const float* W2 = (const float*)d_in[2];   // (1,64)
    float* out = (float*)d_out;                // (8,256,512)

    cudaFuncSetAttribute(proj_kernel,
                         cudaFuncAttributeMaxDynamicSharedMemorySize,
                         PROJ_SMEM_BYTES);
    proj_kernel<<<BB * (LL / 16), 512, PROJ_SMEM_BYTES>>>(x, W1);

    cudaFuncSetAttribute(attn_kernel,
                         cudaFuncAttributeMaxDynamicSharedMemorySize,
                         SMEM2_BYTES);
    attn_kernel<<<BB * (LL / IPB), 1024, SMEM2_BYTES>>>(x, W2, out);
}